// round 3
// baseline (speedup 1.0000x reference)
#include <cuda_runtime.h>
#include <cuda_bf16.h>
#include <cstdint>

#define HID 128
#define NDIM 32
#define EDIM 16
#define MAXN 100000
#define MAXG 1024

// ---------------- scratch (static device globals; no allocs) ----------------
__device__ float g_x[MAXN * HID];       // node states
__device__ float g_agg[MAXN * HID];     // scatter-add accumulator
__device__ float g_pooled[MAXG * HID];  // graph pooled sums
__device__ float g_cnt[MAXG];           // graph node counts

__device__ __forceinline__ float4 relu4(float4 v) {
    return make_float4(fmaxf(v.x, 0.f), fmaxf(v.y, 0.f), fmaxf(v.z, 0.f), fmaxf(v.w, 0.f));
}

// ---------------- zero kernels ----------------
__global__ void k_zero_agg(int n4) {
    int i = blockIdx.x * blockDim.x + threadIdx.x;
    if (i < n4) reinterpret_cast<float4*>(g_agg)[i] = make_float4(0.f, 0.f, 0.f, 0.f);
}
__global__ void k_zero_pool(int G) {
    int i = blockIdx.x * blockDim.x + threadIdx.x;
    if (i < G * (HID / 4)) reinterpret_cast<float4*>(g_pooled)[i] = make_float4(0.f, 0.f, 0.f, 0.f);
    if (i < G) g_cnt[i] = 0.f;
}

// ---------------- node encoder: x = relu(NF @ Wn + bn) ----------------
__global__ void k_node_enc(const float* __restrict__ nf,
                           const float* __restrict__ W,
                           const float* __restrict__ b, int N) {
    __shared__ float sW[NDIM * HID];
    __shared__ float sb[HID];
    int t = threadIdx.x;
    for (int i = t; i < NDIM * HID; i += blockDim.x) sW[i] = W[i];
    if (t < HID) sb[t] = b[t];
    __syncthreads();

    int warp = (blockIdx.x * blockDim.x + t) >> 5;
    int lane = t & 31;
    if (warp >= N) return;

    float myk = nf[(size_t)warp * NDIM + lane];
    int c0 = lane * 4;
    float4 acc = make_float4(sb[c0], sb[c0 + 1], sb[c0 + 2], sb[c0 + 3]);
#pragma unroll
    for (int k = 0; k < NDIM; k++) {
        float v = __shfl_sync(0xffffffffu, myk, k);
        float4 w = *reinterpret_cast<const float4*>(&sW[k * HID + c0]);
        acc.x = fmaf(v, w.x, acc.x);
        acc.y = fmaf(v, w.y, acc.y);
        acc.z = fmaf(v, w.z, acc.z);
        acc.w = fmaf(v, w.w, acc.w);
    }
    *reinterpret_cast<float4*>(&g_x[(size_t)warp * HID + c0]) = relu4(acc);
}

// ---------------- edge phase: agg[dst] += relu(x[src] + EF@We + be) ----------------
// grid-stride, one warp per edge per iter. We held in REGISTERS (64/lane),
// amortized over ~hundreds of edges per warp. No smem, no shfl in hot loop.
__global__ void k_edge(const float* __restrict__ ef,
                       const int* __restrict__ ei,
                       const float* __restrict__ We,
                       const float* __restrict__ be, int E) {
    int lane = threadIdx.x & 31;
    int c0 = lane * 4;
    float4 w[EDIM];
#pragma unroll
    for (int k = 0; k < EDIM; k++)
        w[k] = *reinterpret_cast<const float4*>(&We[k * HID + c0]);
    float4 bias = *reinterpret_cast<const float4*>(&be[c0]);

    int nwarps = (gridDim.x * blockDim.x) >> 5;
    for (int e = (blockIdx.x * blockDim.x + threadIdx.x) >> 5; e < E; e += nwarps) {
        int src = __ldg(ei + e);
        int dst = __ldg(ei + E + e);

        const float4* efv = reinterpret_cast<const float4*>(ef + (size_t)e * EDIM);
        float4 f0 = __ldg(efv + 0);
        float4 f1 = __ldg(efv + 1);
        float4 f2 = __ldg(efv + 2);
        float4 f3 = __ldg(efv + 3);
        float fv[EDIM] = {f0.x, f0.y, f0.z, f0.w, f1.x, f1.y, f1.z, f1.w,
                          f2.x, f2.y, f2.z, f2.w, f3.x, f3.y, f3.z, f3.w};
        float4 acc = bias;
#pragma unroll
        for (int k = 0; k < EDIM; k++) {
            acc.x = fmaf(fv[k], w[k].x, acc.x);
            acc.y = fmaf(fv[k], w[k].y, acc.y);
            acc.z = fmaf(fv[k], w[k].z, acc.z);
            acc.w = fmaf(fv[k], w[k].w, acc.w);
        }
        float4 xs = *reinterpret_cast<const float4*>(&g_x[(size_t)src * HID + c0]);
        float4 m = make_float4(fmaxf(xs.x + acc.x, 0.f), fmaxf(xs.y + acc.y, 0.f),
                               fmaxf(xs.z + acc.z, 0.f), fmaxf(xs.w + acc.w, 0.f));
        atomicAdd(reinterpret_cast<float4*>(&g_agg[(size_t)dst * HID]) + lane, m);
    }
}

// ---------------- node MLP: x = relu( relu(((1+eps)x+agg)@W1+b1) @ W2 + b2 ) ----------------
#define TILE_M 64
#define HPAD 132
__global__ void k_node_mlp(const float* __restrict__ W1,
                           const float* __restrict__ b1,
                           const float* __restrict__ W2,
                           const float* __restrict__ b2,
                           const float* __restrict__ epsp, int l, int N) {
    extern __shared__ float sm[];
    float* sW1 = sm;
    float* sW2 = sm + 16384;
    float* sb1 = sm + 32768;
    float* sb2 = sm + 32896;
    float* shA = sm + 33024;
    float* shB = shA + TILE_M * HPAD;

    int t = threadIdx.x;
    {
        const float4* w1v = reinterpret_cast<const float4*>(W1);
        const float4* w2v = reinterpret_cast<const float4*>(W2);
        float4* s1 = reinterpret_cast<float4*>(sW1);
        float4* s2 = reinterpret_cast<float4*>(sW2);
        for (int i = t; i < HID * HID / 4; i += blockDim.x) { s1[i] = w1v[i]; s2[i] = w2v[i]; }
        if (t < HID) { sb1[t] = b1[t]; sb2[t] = b2[t]; }
    }
    float epv = 1.0f + epsp[l];

    int node0 = blockIdx.x * TILE_M;
    for (int i = t; i < TILE_M * HID; i += blockDim.x) {
        int m = i >> 7, k = i & 127;
        int node = node0 + m;
        float v = 0.f;
        if (node < N) {
            size_t off = (size_t)node * HID + k;
            v = fmaf(epv, g_x[off], g_agg[off]);
        }
        shA[m * HPAD + k] = v;
    }
    __syncthreads();

    int cg = t & 15, rg = t >> 4;
    int c0 = cg * 8, r0 = rg * 4;

    {
        float acc[4][8];
#pragma unroll
        for (int i = 0; i < 4; i++)
#pragma unroll
            for (int j = 0; j < 8; j++) acc[i][j] = sb1[c0 + j];
#pragma unroll 4
        for (int k = 0; k < HID; k++) {
            float a0 = shA[(r0 + 0) * HPAD + k];
            float a1 = shA[(r0 + 1) * HPAD + k];
            float a2 = shA[(r0 + 2) * HPAD + k];
            float a3 = shA[(r0 + 3) * HPAD + k];
            float4 w0 = *reinterpret_cast<const float4*>(&sW1[k * HID + c0]);
            float4 w1 = *reinterpret_cast<const float4*>(&sW1[k * HID + c0 + 4]);
            float wv[8] = {w0.x, w0.y, w0.z, w0.w, w1.x, w1.y, w1.z, w1.w};
#pragma unroll
            for (int j = 0; j < 8; j++) {
                acc[0][j] = fmaf(a0, wv[j], acc[0][j]);
                acc[1][j] = fmaf(a1, wv[j], acc[1][j]);
                acc[2][j] = fmaf(a2, wv[j], acc[2][j]);
                acc[3][j] = fmaf(a3, wv[j], acc[3][j]);
            }
        }
#pragma unroll
        for (int i = 0; i < 4; i++)
#pragma unroll
            for (int j = 0; j < 8; j++)
                shB[(r0 + i) * HPAD + c0 + j] = fmaxf(acc[i][j], 0.f);
    }
    __syncthreads();

    {
        float acc[4][8];
#pragma unroll
        for (int i = 0; i < 4; i++)
#pragma unroll
            for (int j = 0; j < 8; j++) acc[i][j] = sb2[c0 + j];
#pragma unroll 4
        for (int k = 0; k < HID; k++) {
            float a0 = shB[(r0 + 0) * HPAD + k];
            float a1 = shB[(r0 + 1) * HPAD + k];
            float a2 = shB[(r0 + 2) * HPAD + k];
            float a3 = shB[(r0 + 3) * HPAD + k];
            float4 w0 = *reinterpret_cast<const float4*>(&sW2[k * HID + c0]);
            float4 w1 = *reinterpret_cast<const float4*>(&sW2[k * HID + c0 + 4]);
            float wv[8] = {w0.x, w0.y, w0.z, w0.w, w1.x, w1.y, w1.z, w1.w};
#pragma unroll
            for (int j = 0; j < 8; j++) {
                acc[0][j] = fmaf(a0, wv[j], acc[0][j]);
                acc[1][j] = fmaf(a1, wv[j], acc[1][j]);
                acc[2][j] = fmaf(a2, wv[j], acc[2][j]);
                acc[3][j] = fmaf(a3, wv[j], acc[3][j]);
            }
        }
#pragma unroll
        for (int i = 0; i < 4; i++) {
            int node = node0 + r0 + i;
            if (node < N) {
                float4 o0 = make_float4(fmaxf(acc[i][0], 0.f), fmaxf(acc[i][1], 0.f),
                                        fmaxf(acc[i][2], 0.f), fmaxf(acc[i][3], 0.f));
                float4 o1 = make_float4(fmaxf(acc[i][4], 0.f), fmaxf(acc[i][5], 0.f),
                                        fmaxf(acc[i][6], 0.f), fmaxf(acc[i][7], 0.f));
                *reinterpret_cast<float4*>(&g_x[(size_t)node * HID + c0]) = o0;
                *reinterpret_cast<float4*>(&g_x[(size_t)node * HID + c0 + 4]) = o1;
            }
        }
    }
}
#define MLP_SMEM_BYTES ((33024 + 2 * TILE_M * HPAD) * sizeof(float))

// ---------------- pooling ----------------
__global__ void k_pool(const int* __restrict__ batch, int N) {
    int warp = (blockIdx.x * blockDim.x + threadIdx.x) >> 5;
    int lane = threadIdx.x & 31;
    if (warp >= N) return;
    int g = batch[warp];
    if (lane == 0) atomicAdd(&g_cnt[g], 1.0f);
    float4 v = *reinterpret_cast<const float4*>(&g_x[(size_t)warp * HID + lane * 4]);
    atomicAdd(reinterpret_cast<float4*>(&g_pooled[(size_t)g * HID]) + lane, v);
}

// ---------------- readout ----------------
__global__ void k_out(const float* __restrict__ fw1, const float* __restrict__ fb1,
                      const float* __restrict__ fw2, const float* __restrict__ fb2,
                      float* __restrict__ out, int G) {
    int warp = (blockIdx.x * blockDim.x + threadIdx.x) >> 5;
    int lane = threadIdx.x & 31;
    if (warp >= G) return;

    float inv = 1.0f / fmaxf(g_cnt[warp], 1.0f);
    float p[4];
#pragma unroll
    for (int i = 0; i < 4; i++) p[i] = g_pooled[(size_t)warp * HID + i * 32 + lane] * inv;

    int c0 = lane * 4;
    float4 acc = make_float4(fb1[c0], fb1[c0 + 1], fb1[c0 + 2], fb1[c0 + 3]);
#pragma unroll
    for (int k = 0; k < HID; k++) {
        float v = __shfl_sync(0xffffffffu, p[k >> 5], k & 31);
        float4 w = *reinterpret_cast<const float4*>(&fw1[k * HID + c0]);
        acc.x = fmaf(v, w.x, acc.x);
        acc.y = fmaf(v, w.y, acc.y);
        acc.z = fmaf(v, w.z, acc.z);
        acc.w = fmaf(v, w.w, acc.w);
    }
    acc = relu4(acc);
    float partial = acc.x * fw2[c0] + acc.y * fw2[c0 + 1] + acc.z * fw2[c0 + 2] + acc.w * fw2[c0 + 3];
#pragma unroll
    for (int s = 16; s > 0; s >>= 1) partial += __shfl_xor_sync(0xffffffffu, partial, s);
    if (lane == 0) out[warp] = partial + fb2[0];
}

// ---------------- launch ----------------
extern "C" void kernel_launch(void* const* d_in, const int* in_sizes, int n_in,
                              void* d_out, int out_size) {
    const float* NF  = (const float*)d_in[0];
    const float* EF  = (const float*)d_in[1];
    const int*   EI  = (const int*)d_in[2];
    const int*   BA  = (const int*)d_in[3];
    const float* Wn  = (const float*)d_in[4];
    const float* bn  = (const float*)d_in[5];
    const float* We  = (const float*)d_in[6];
    const float* be  = (const float*)d_in[7];
    const float* cw1 = (const float*)d_in[8];
    const float* cb1 = (const float*)d_in[9];
    const float* cw2 = (const float*)d_in[10];
    const float* cb2 = (const float*)d_in[11];
    const float* eps = (const float*)d_in[12];
    const float* fw1 = (const float*)d_in[13];
    const float* fb1 = (const float*)d_in[14];
    const float* fw2 = (const float*)d_in[15];
    const float* fb2 = (const float*)d_in[16];
    float* out = (float*)d_out;

    int N = in_sizes[0] / NDIM;
    int E = in_sizes[1] / EDIM;
    int L = in_sizes[12];
    int G = out_size;

    static bool attr_done = false;
    if (!attr_done) {
        cudaFuncSetAttribute(k_node_mlp, cudaFuncAttributeMaxDynamicSharedMemorySize,
                             (int)MLP_SMEM_BYTES);
        attr_done = true;
    }

    const int THREADS = 256;
    int nodeWarpBlocks = (N + 7) / 8;

    k_zero_pool<<<(G * HID / 4 + THREADS - 1) / THREADS, THREADS>>>(G);
    k_node_enc<<<nodeWarpBlocks, THREADS>>>(NF, Wn, bn, N);

    for (int l = 0; l < L; l++) {
        int agg4 = N * HID / 4;
        k_zero_agg<<<(agg4 + THREADS - 1) / THREADS, THREADS>>>(agg4);
        k_edge<<<2048, THREADS>>>(EF, EI, We, be, E);
        k_node_mlp<<<(N + TILE_M - 1) / TILE_M, THREADS, MLP_SMEM_BYTES>>>(
            cw1 + (size_t)l * HID * HID, cb1 + (size_t)l * HID,
            cw2 + (size_t)l * HID * HID, cb2 + (size_t)l * HID, eps, l, N);
    }

    k_pool<<<nodeWarpBlocks, THREADS>>>(BA, N);
    k_out<<<(G + 7) / 8, THREADS>>>(fw1, fb1, fw2, fb2, out, G);
}

// round 5
// speedup vs baseline: 1.7317x; 1.7317x over previous
#include <cuda_runtime.h>
#include <cuda_bf16.h>
#include <cstdint>

#define HID 128
#define NDIM 32
#define EDIM 16
#define MAXN 100000
#define MAXG 1024

// ---------------- scratch (static device globals; no allocs) ----------------
__device__ float g_x[MAXN * HID];       // node states
__device__ float g_agg[MAXN * HID];     // scatter-add accumulator
__device__ float g_pooled[MAXG * HID];  // graph pooled sums
__device__ float g_cnt[MAXG];           // graph node counts

__device__ __forceinline__ float4 relu4(float4 v) {
    return make_float4(fmaxf(v.x, 0.f), fmaxf(v.y, 0.f), fmaxf(v.z, 0.f), fmaxf(v.w, 0.f));
}

#define FMA4(acc, s, wk)                  \
    acc.x = fmaf(s, wk.x, acc.x);         \
    acc.y = fmaf(s, wk.y, acc.y);         \
    acc.z = fmaf(s, wk.z, acc.z);         \
    acc.w = fmaf(s, wk.w, acc.w);

// ---------------- zero kernels ----------------
__global__ void k_zero_agg(int n4) {
    int i = blockIdx.x * blockDim.x + threadIdx.x;
    if (i < n4) reinterpret_cast<float4*>(g_agg)[i] = make_float4(0.f, 0.f, 0.f, 0.f);
}
__global__ void k_zero_pool(int G) {
    int i = blockIdx.x * blockDim.x + threadIdx.x;
    if (i < G * (HID / 4)) reinterpret_cast<float4*>(g_pooled)[i] = make_float4(0.f, 0.f, 0.f, 0.f);
    if (i < G) g_cnt[i] = 0.f;
}

// ---------------- node encoder: x = relu(NF @ Wn + bn) ----------------
__global__ void k_node_enc(const float* __restrict__ nf,
                           const float* __restrict__ W,
                           const float* __restrict__ b, int N) {
    __shared__ float sW[NDIM * HID];
    __shared__ float sb[HID];
    int t = threadIdx.x;
    for (int i = t; i < NDIM * HID; i += blockDim.x) sW[i] = W[i];
    if (t < HID) sb[t] = b[t];
    __syncthreads();

    int warp = (blockIdx.x * blockDim.x + t) >> 5;
    int lane = t & 31;
    if (warp >= N) return;

    float myk = nf[(size_t)warp * NDIM + lane];
    int c0 = lane * 4;
    float4 acc = make_float4(sb[c0], sb[c0 + 1], sb[c0 + 2], sb[c0 + 3]);
#pragma unroll
    for (int k = 0; k < NDIM; k++) {
        float v = __shfl_sync(0xffffffffu, myk, k);
        float4 w = *reinterpret_cast<const float4*>(&sW[k * HID + c0]);
        FMA4(acc, v, w);
    }
    *reinterpret_cast<float4*>(&g_x[(size_t)warp * HID + c0]) = relu4(acc);
}

// ---------------- edge phase: agg[dst] += relu(x[src] + EF@We + be) ----------------
// Software-pipelined grid-stride warp-per-edge:
//  - weights in registers (16 x float4 per lane; lane owns 4 output cols)
//  - next edge's indices + edge features prefetched one iteration ahead
//  - x[src] gather issued first so its L2 latency overlaps the 64-FMA matvec
__global__ void __launch_bounds__(256, 2) k_edge(const float* __restrict__ ef,
                                                 const int* __restrict__ ei,
                                                 const float* __restrict__ We,
                                                 const float* __restrict__ be, int E) {
    int lane = threadIdx.x & 31;
    int c0 = lane * 4;
    float4 w[EDIM];
#pragma unroll
    for (int k = 0; k < EDIM; k++)
        w[k] = __ldg(reinterpret_cast<const float4*>(&We[k * HID + c0]));
    float4 bias = __ldg(reinterpret_cast<const float4*>(&be[c0]));

    int stride = (gridDim.x * blockDim.x) >> 5;
    int e = (blockIdx.x * blockDim.x + threadIdx.x) >> 5;
    if (e >= E) return;

    // prologue: load current edge's metadata
    int src = __ldg(ei + e);
    int dst = __ldg(ei + E + e);
    const float4* efv = reinterpret_cast<const float4*>(ef) + (size_t)e * 4;
    float4 f0 = __ldg(efv + 0), f1 = __ldg(efv + 1), f2 = __ldg(efv + 2), f3 = __ldg(efv + 3);

    while (true) {
        // 1) gather for CURRENT edge first (longest-latency consumer)
        float4 xs = __ldg(reinterpret_cast<const float4*>(&g_x[(size_t)src * HID + c0]));
        int dst_cur = dst;

        // 2) prefetch NEXT edge's indices + features
        int e_n = e + stride;
        int src_n = 0, dst_n = 0;
        float4 g0 = f0, g1 = f1, g2 = f2, g3 = f3;
        bool have_next = (e_n < E);
        if (have_next) {
            src_n = __ldg(ei + e_n);
            dst_n = __ldg(ei + E + e_n);
            const float4* gv = reinterpret_cast<const float4*>(ef) + (size_t)e_n * 4;
            g0 = __ldg(gv + 0); g1 = __ldg(gv + 1); g2 = __ldg(gv + 2); g3 = __ldg(gv + 3);
        }

        // 3) edge-embedding matvec (overlaps the in-flight loads)
        float4 acc = bias;
        FMA4(acc, f0.x, w[0]);  FMA4(acc, f0.y, w[1]);  FMA4(acc, f0.z, w[2]);  FMA4(acc, f0.w, w[3]);
        FMA4(acc, f1.x, w[4]);  FMA4(acc, f1.y, w[5]);  FMA4(acc, f1.z, w[6]);  FMA4(acc, f1.w, w[7]);
        FMA4(acc, f2.x, w[8]);  FMA4(acc, f2.y, w[9]);  FMA4(acc, f2.z, w[10]); FMA4(acc, f2.w, w[11]);
        FMA4(acc, f3.x, w[12]); FMA4(acc, f3.y, w[13]); FMA4(acc, f3.z, w[14]); FMA4(acc, f3.w, w[15]);

        float4 m = make_float4(fmaxf(xs.x + acc.x, 0.f), fmaxf(xs.y + acc.y, 0.f),
                               fmaxf(xs.z + acc.z, 0.f), fmaxf(xs.w + acc.w, 0.f));
        atomicAdd(reinterpret_cast<float4*>(&g_agg[(size_t)dst_cur * HID]) + lane, m);

        if (!have_next) break;
        e = e_n; src = src_n; dst = dst_n;
        f0 = g0; f1 = g1; f2 = g2; f3 = g3;
    }
}

// ---------------- node MLP: x = relu( relu(((1+eps)x+agg)@W1+b1) @ W2 + b2 ) ----------------
#define TILE_M 64
#define HPAD 132
__global__ void k_node_mlp(const float* __restrict__ W1,
                           const float* __restrict__ b1,
                           const float* __restrict__ W2,
                           const float* __restrict__ b2,
                           const float* __restrict__ epsp, int l, int N) {
    extern __shared__ float sm[];
    float* sW1 = sm;
    float* sW2 = sm + 16384;
    float* sb1 = sm + 32768;
    float* sb2 = sm + 32896;
    float* shA = sm + 33024;
    float* shB = shA + TILE_M * HPAD;

    int t = threadIdx.x;
    {
        const float4* w1v = reinterpret_cast<const float4*>(W1);
        const float4* w2v = reinterpret_cast<const float4*>(W2);
        float4* s1 = reinterpret_cast<float4*>(sW1);
        float4* s2 = reinterpret_cast<float4*>(sW2);
        for (int i = t; i < HID * HID / 4; i += blockDim.x) { s1[i] = w1v[i]; s2[i] = w2v[i]; }
        if (t < HID) { sb1[t] = b1[t]; sb2[t] = b2[t]; }
    }
    float epv = 1.0f + epsp[l];

    int node0 = blockIdx.x * TILE_M;
    for (int i = t; i < TILE_M * HID; i += blockDim.x) {
        int m = i >> 7, k = i & 127;
        int node = node0 + m;
        float v = 0.f;
        if (node < N) {
            size_t off = (size_t)node * HID + k;
            v = fmaf(epv, g_x[off], g_agg[off]);
        }
        shA[m * HPAD + k] = v;
    }
    __syncthreads();

    int cg = t & 15, rg = t >> 4;
    int c0 = cg * 8, r0 = rg * 4;

    {
        float acc[4][8];
#pragma unroll
        for (int i = 0; i < 4; i++)
#pragma unroll
            for (int j = 0; j < 8; j++) acc[i][j] = sb1[c0 + j];
#pragma unroll 4
        for (int k = 0; k < HID; k++) {
            float a0 = shA[(r0 + 0) * HPAD + k];
            float a1 = shA[(r0 + 1) * HPAD + k];
            float a2 = shA[(r0 + 2) * HPAD + k];
            float a3 = shA[(r0 + 3) * HPAD + k];
            float4 w0 = *reinterpret_cast<const float4*>(&sW1[k * HID + c0]);
            float4 w1 = *reinterpret_cast<const float4*>(&sW1[k * HID + c0 + 4]);
            float wv[8] = {w0.x, w0.y, w0.z, w0.w, w1.x, w1.y, w1.z, w1.w};
#pragma unroll
            for (int j = 0; j < 8; j++) {
                acc[0][j] = fmaf(a0, wv[j], acc[0][j]);
                acc[1][j] = fmaf(a1, wv[j], acc[1][j]);
                acc[2][j] = fmaf(a2, wv[j], acc[2][j]);
                acc[3][j] = fmaf(a3, wv[j], acc[3][j]);
            }
        }
#pragma unroll
        for (int i = 0; i < 4; i++)
#pragma unroll
            for (int j = 0; j < 8; j++)
                shB[(r0 + i) * HPAD + c0 + j] = fmaxf(acc[i][j], 0.f);
    }
    __syncthreads();

    {
        float acc[4][8];
#pragma unroll
        for (int i = 0; i < 4; i++)
#pragma unroll
            for (int j = 0; j < 8; j++) acc[i][j] = sb2[c0 + j];
#pragma unroll 4
        for (int k = 0; k < HID; k++) {
            float a0 = shB[(r0 + 0) * HPAD + k];
            float a1 = shB[(r0 + 1) * HPAD + k];
            float a2 = shB[(r0 + 2) * HPAD + k];
            float a3 = shB[(r0 + 3) * HPAD + k];
            float4 w0 = *reinterpret_cast<const float4*>(&sW2[k * HID + c0]);
            float4 w1 = *reinterpret_cast<const float4*>(&sW2[k * HID + c0 + 4]);
            float wv[8] = {w0.x, w0.y, w0.z, w0.w, w1.x, w1.y, w1.z, w1.w};
#pragma unroll
            for (int j = 0; j < 8; j++) {
                acc[0][j] = fmaf(a0, wv[j], acc[0][j]);
                acc[1][j] = fmaf(a1, wv[j], acc[1][j]);
                acc[2][j] = fmaf(a2, wv[j], acc[2][j]);
                acc[3][j] = fmaf(a3, wv[j], acc[3][j]);
            }
        }
#pragma unroll
        for (int i = 0; i < 4; i++) {
            int node = node0 + r0 + i;
            if (node < N) {
                float4 o0 = make_float4(fmaxf(acc[i][0], 0.f), fmaxf(acc[i][1], 0.f),
                                        fmaxf(acc[i][2], 0.f), fmaxf(acc[i][3], 0.f));
                float4 o1 = make_float4(fmaxf(acc[i][4], 0.f), fmaxf(acc[i][5], 0.f),
                                        fmaxf(acc[i][6], 0.f), fmaxf(acc[i][7], 0.f));
                *reinterpret_cast<float4*>(&g_x[(size_t)node * HID + c0]) = o0;
                *reinterpret_cast<float4*>(&g_x[(size_t)node * HID + c0 + 4]) = o1;
            }
        }
    }
}
#define MLP_SMEM_BYTES ((33024 + 2 * TILE_M * HPAD) * sizeof(float))

// ---------------- pooling ----------------
__global__ void k_pool(const int* __restrict__ batch, int N) {
    int warp = (blockIdx.x * blockDim.x + threadIdx.x) >> 5;
    int lane = threadIdx.x & 31;
    if (warp >= N) return;
    int g = batch[warp];
    if (lane == 0) atomicAdd(&g_cnt[g], 1.0f);
    float4 v = *reinterpret_cast<const float4*>(&g_x[(size_t)warp * HID + lane * 4]);
    atomicAdd(reinterpret_cast<float4*>(&g_pooled[(size_t)g * HID]) + lane, v);
}

// ---------------- readout ----------------
__global__ void k_out(const float* __restrict__ fw1, const float* __restrict__ fb1,
                      const float* __restrict__ fw2, const float* __restrict__ fb2,
                      float* __restrict__ out, int G) {
    int warp = (blockIdx.x * blockDim.x + threadIdx.x) >> 5;
    int lane = threadIdx.x & 31;
    if (warp >= G) return;

    float inv = 1.0f / fmaxf(g_cnt[warp], 1.0f);
    float p[4];
#pragma unroll
    for (int i = 0; i < 4; i++) p[i] = g_pooled[(size_t)warp * HID + i * 32 + lane] * inv;

    int c0 = lane * 4;
    float4 acc = make_float4(fb1[c0], fb1[c0 + 1], fb1[c0 + 2], fb1[c0 + 3]);
#pragma unroll
    for (int k = 0; k < HID; k++) {
        float v = __shfl_sync(0xffffffffu, p[k >> 5], k & 31);
        float4 w = *reinterpret_cast<const float4*>(&fw1[k * HID + c0]);
        FMA4(acc, v, w);
    }
    acc = relu4(acc);
    float partial = acc.x * fw2[c0] + acc.y * fw2[c0 + 1] + acc.z * fw2[c0 + 2] + acc.w * fw2[c0 + 3];
#pragma unroll
    for (int s = 16; s > 0; s >>= 1) partial += __shfl_xor_sync(0xffffffffu, partial, s);
    if (lane == 0) out[warp] = partial + fb2[0];
}

// ---------------- launch ----------------
extern "C" void kernel_launch(void* const* d_in, const int* in_sizes, int n_in,
                              void* d_out, int out_size) {
    const float* NF  = (const float*)d_in[0];
    const float* EF  = (const float*)d_in[1];
    const int*   EI  = (const int*)d_in[2];
    const int*   BA  = (const int*)d_in[3];
    const float* Wn  = (const float*)d_in[4];
    const float* bn  = (const float*)d_in[5];
    const float* We  = (const float*)d_in[6];
    const float* be  = (const float*)d_in[7];
    const float* cw1 = (const float*)d_in[8];
    const float* cb1 = (const float*)d_in[9];
    const float* cw2 = (const float*)d_in[10];
    const float* cb2 = (const float*)d_in[11];
    const float* eps = (const float*)d_in[12];
    const float* fw1 = (const float*)d_in[13];
    const float* fb1 = (const float*)d_in[14];
    const float* fw2 = (const float*)d_in[15];
    const float* fb2 = (const float*)d_in[16];
    float* out = (float*)d_out;

    int N = in_sizes[0] / NDIM;
    int E = in_sizes[1] / EDIM;
    int L = in_sizes[12];
    int G = out_size;

    static bool attr_done = false;
    if (!attr_done) {
        cudaFuncSetAttribute(k_node_mlp, cudaFuncAttributeMaxDynamicSharedMemorySize,
                             (int)MLP_SMEM_BYTES);
        attr_done = true;
    }

    const int THREADS = 256;
    int nodeWarpBlocks = (N + 7) / 8;

    k_zero_pool<<<(G * HID / 4 + THREADS - 1) / THREADS, THREADS>>>(G);
    k_node_enc<<<nodeWarpBlocks, THREADS>>>(NF, Wn, bn, N);

    for (int l = 0; l < L; l++) {
        int agg4 = N * HID / 4;
        k_zero_agg<<<(agg4 + THREADS - 1) / THREADS, THREADS>>>(agg4);
        k_edge<<<1184, THREADS>>>(EF, EI, We, be, E);  // 4 waves @ 2 blocks/SM
        k_node_mlp<<<(N + TILE_M - 1) / TILE_M, THREADS, MLP_SMEM_BYTES>>>(
            cw1 + (size_t)l * HID * HID, cb1 + (size_t)l * HID,
            cw2 + (size_t)l * HID * HID, cb2 + (size_t)l * HID, eps, l, N);
    }

    k_pool<<<nodeWarpBlocks, THREADS>>>(BA, N);
    k_out<<<(G + 7) / 8, THREADS>>>(fw1, fb1, fw2, fb2, out, G);
}